// round 12
// baseline (speedup 1.0000x reference)
#include <cuda_runtime.h>
#include <math.h>

// Shape fixed by reference: B=2, L=2048, H=16, E=64
#define B_  2
#define L_  2048
#define H_  16
#define E_  64
#define BH_ 32            // B*H chains
#define CH_ 64            // chunk length along s
#define NC_ 32            // chunks per chain
#define HE_ 1024          // H*E row stride in floats
#define NBLK (BH_ * NC_)  // 1024 blocks
#define NSUB 4            // sub-groups (16 rows each)
#define RPS  16           // rows per sub (K1)

// Scratch (__device__ globals; no allocations allowed)
__device__ float  g_E   [BH_ * L_];          // e-scores
__device__ float4 g_agg [NBLK * 16];         // per-chunk sum of e*V (64 ch)
__device__ float  g_aggE[NBLK];              // per-chunk sum of e
__device__ float4 g_sub [NBLK * NSUB * 16];  // EXCLUSIVE cross-sub EV prefix
__device__ float4 g_pre [NBLK * 16];         // EXCLUSIVE cross-chunk EV prefix
__device__ float  g_rcp [BH_ * L_];          // 1 / cumulative-E per row

// ---------------- K1: e-scores + chunk aggregates + sub prefixes (proven) --
__global__ __launch_bounds__(256, 8) void k_aggregate(
    const float* __restrict__ keys,
    const float* __restrict__ values,
    const float* __restrict__ w_score)
{
    __shared__ float sV[CH_ * E_];     // 16 KB V tile
    __shared__ float se[CH_];
    __shared__ float spEV[NSUB * E_];
    __shared__ float spE[NSUB];

    const int tid = threadIdx.x;
    const int blk = blockIdx.x;
    const int bh  = blk >> 5;          // / NC_
    const int c   = blk & 31;          // % NC_
    const int b   = bh >> 4;
    const int h   = bh & 15;
    const int base = ((b * L_ + c * CH_) * H_ + h) * E_;

    const int d   = tid & 63;
    const int sub = tid >> 6;
    const int r0  = sub * RPS;

    // e[row] = exp(0.125 * dot(K[row], w_k)); 4 threads per row
    {
        const int row = tid >> 2, q = tid & 3;
        const float4* kq = reinterpret_cast<const float4*>(
            keys + base + row * HE_ + q * 16);
        const float4* wq = reinterpret_cast<const float4*>(
            w_score + E_ + q * 16);
        float dot = 0.f;
        #pragma unroll
        for (int j = 0; j < 4; j++) {
            const float4 k4 = kq[j];
            const float4 w4 = wq[j];
            dot += k4.x * w4.x + k4.y * w4.y + k4.z * w4.z + k4.w * w4.w;
        }
        dot += __shfl_xor_sync(0xffffffffu, dot, 1);
        dot += __shfl_xor_sync(0xffffffffu, dot, 2);
        if (q == 0) {
            const float e = __expf(dot * 0.125f);
            se[row] = e;
            g_E[bh * L_ + c * CH_ + row] = e;
        }
    }

    // stage V tile (float4, coalesced)
    {
        const float4* vg = reinterpret_cast<const float4*>(values + base);
        float4* sv4 = reinterpret_cast<float4*>(sV);
        #pragma unroll
        for (int i = 0; i < 4; i++) {
            const int idx = tid + i * 256;
            sv4[idx] = vg[(idx >> 4) * (HE_ / 4) + (idx & 15)];
        }
    }
    __syncthreads();

    // per-sub partial aggregates over 16 rows
    {
        float sumE = 0.f, sumEV = 0.f;
        #pragma unroll
        for (int r = 0; r < RPS; r++) {
            const float e = se[r0 + r];
            sumE += e;
            sumEV = fmaf(e, sV[(r0 + r) * E_ + d], sumEV);
        }
        spEV[sub * E_ + d] = sumEV;
        if (d == 0) spE[sub] = sumE;
    }
    __syncthreads();

    // exclusive cross-sub prefix -> g_sub
    {
        float exc = 0.f;
        #pragma unroll
        for (int s = 0; s < NSUB - 1; s++)
            if (s < sub) exc += spEV[s * E_ + d];
        reinterpret_cast<float*>(g_sub)[(blk * NSUB + sub) * E_ + d] = exc;
    }

    // block aggregate
    if (tid < E_) {
        reinterpret_cast<float*>(g_agg)[blk * E_ + tid] =
            spEV[tid] + spEV[E_ + tid] + spEV[2 * E_ + tid] + spEV[3 * E_ + tid];
        if (tid == 0)
            g_aggE[blk] = spE[0] + spE[1] + spE[2] + spE[3];
    }
}

// ---------------- K_mid: per-chain chunk-prefix scan + row reciprocals -----
__global__ __launch_bounds__(256, 1) void k_mid()
{
    __shared__ float sA[NC_ * E_];     // 8 KB
    __shared__ float sB[NC_ * E_];     // 8 KB
    __shared__ float scE[NC_];         // exclusive chunk-E prefix

    const int bh  = blockIdx.x;
    const int tid = threadIdx.x;

    // load chunk EV aggregates: layout idx = c*64 + d
    const float* ga = reinterpret_cast<const float*>(g_agg) + bh * NC_ * E_;
    #pragma unroll
    for (int i = 0; i < 8; i++) sA[tid + i * 256] = ga[tid + i * 256];

    // warp 0: exclusive scan of chunk E sums
    if (tid < 32) {
        const float v = g_aggE[bh * NC_ + tid];
        float incl = v;
        #pragma unroll
        for (int o = 1; o < 32; o <<= 1) {
            const float t = __shfl_up_sync(0xffffffffu, incl, o);
            if (tid >= o) incl += t;
        }
        scE[tid] = incl - v;
    }
    __syncthreads();

    // Hillis-Steele inclusive scan over chunk axis
    float* src = sA; float* dst = sB;
    #pragma unroll
    for (int o = 1; o < NC_; o <<= 1) {
        #pragma unroll
        for (int i = 0; i < 8; i++) {
            const int idx = tid + i * 256;
            float v = src[idx];
            if ((idx >> 6) >= o) v += src[idx - (o << 6)];
            dst[idx] = v;
        }
        __syncthreads();
        float* t = src; src = dst; dst = t;
    }

    // exclusive: chunk c gets inclusive[c-1]
    float* gp = reinterpret_cast<float*>(g_pre) + bh * NC_ * E_;
    #pragma unroll
    for (int i = 0; i < 8; i++) {
        const int idx = tid + i * 256;
        gp[idx] = (idx >= E_) ? src[idx - E_] : 0.f;
    }

    // reciprocals: warp w handles chunks 4w..4w+3
    const int w = tid >> 5, lane = tid & 31;
    #pragma unroll
    for (int k = 0; k < 4; k++) {
        const int c = w * 4 + k;
        const float2 e2 = reinterpret_cast<const float2*>(
            g_E + bh * L_ + c * CH_)[lane];
        const float p = e2.x + e2.y;
        float incl = p;
        #pragma unroll
        for (int o = 1; o < 32; o <<= 1) {
            const float t = __shfl_up_sync(0xffffffffu, incl, o);
            if (lane >= o) incl += t;
        }
        const float excl = incl - p;
        const float pe = scE[c];
        float2 rr;
        rr.x = __fdividef(1.f, pe + excl + e2.x);
        rr.y = __fdividef(1.f, pe + incl);
        reinterpret_cast<float2*>(g_rcp + bh * L_ + c * CH_)[lane] = rr;
    }
}

// ---------------- K2: pure-streaming float4 output (no scans, no divides) --
__global__ __launch_bounds__(256, 6) void k_output(
    const float* __restrict__ values,
    float* __restrict__ out)
{
    __shared__ float  se[CH_];
    __shared__ float  sr[CH_];
    __shared__ float4 sPart[16 * 16];   // quad EV partials [q][d4]

    const int tid = threadIdx.x;
    const int blk = blockIdx.x;
    const int bh  = blk >> 5;
    const int c   = blk & 31;
    const int b   = bh >> 4;
    const int h   = bh & 15;
    const int base = ((b * L_ + c * CH_) * H_ + h) * E_;

    const int d4  = tid & 15;           // float4 channel group
    const int q   = tid >> 4;           // quad 0..15 (4 rows)
    const int sub = q >> 2;
    const int qq  = q & 3;
    const int r0  = q * 4;

    // stage e + rcp for this chunk (2 coalesced loads by first 64 threads)
    if (tid < CH_) {
        se[tid] = g_E  [bh * L_ + c * CH_ + tid];
        sr[tid] = g_rcp[bh * L_ + c * CH_ + tid];
    }

    // independent global loads issued before the barrier
    const float4* v4 = reinterpret_cast<const float4*>(values + base);
    float4 vv[4];
    #pragma unroll
    for (int j = 0; j < 4; j++)
        vv[j] = v4[(r0 + j) * (HE_ / 4) + d4];

    float4 acc = g_pre[blk * 16 + d4];                      // cross-chunk
    const float4 gs = g_sub[(blk * NSUB + sub) * 16 + d4];  // cross-sub
    acc.x += gs.x; acc.y += gs.y; acc.z += gs.z; acc.w += gs.w;

    __syncthreads();

    float e[4];
    #pragma unroll
    for (int j = 0; j < 4; j++) e[j] = se[r0 + j];

    // quad EV partial -> smem
    {
        float4 p = make_float4(0.f, 0.f, 0.f, 0.f);
        #pragma unroll
        for (int j = 0; j < 4; j++) {
            p.x = fmaf(e[j], vv[j].x, p.x);
            p.y = fmaf(e[j], vv[j].y, p.y);
            p.z = fmaf(e[j], vv[j].z, p.z);
            p.w = fmaf(e[j], vv[j].w, p.w);
        }
        sPart[q * 16 + d4] = p;
    }
    __syncthreads();

    // add lower quads within this sub (<=3 LDS.128)
    #pragma unroll
    for (int j = 0; j < 3; j++) {
        if (j < qq) {
            const float4 t = sPart[(sub * 4 + j) * 16 + d4];
            acc.x += t.x; acc.y += t.y; acc.z += t.z; acc.w += t.w;
        }
    }

    // 4-row inclusive scan from regs; float4 stores
    float4* o4 = reinterpret_cast<float4*>(out + base);
    #pragma unroll
    for (int j = 0; j < 4; j++) {
        acc.x = fmaf(e[j], vv[j].x, acc.x);
        acc.y = fmaf(e[j], vv[j].y, acc.y);
        acc.z = fmaf(e[j], vv[j].z, acc.z);
        acc.w = fmaf(e[j], vv[j].w, acc.w);
        const float rc = sr[r0 + j];
        float4 res;
        res.x = acc.x * rc; res.y = acc.y * rc;
        res.z = acc.z * rc; res.w = acc.w * rc;
        o4[(r0 + j) * (HE_ / 4) + d4] = res;
    }
}

extern "C" void kernel_launch(void* const* d_in, const int* in_sizes, int n_in,
                              void* d_out, int out_size) {
    // inputs: 0=queries (unused: a_q cancels in softmax), 1=keys, 2=values,
    //         3=w_score, 4=b_score (unused: cancels)
    const float* keys   = (const float*)d_in[1];
    const float* values = (const float*)d_in[2];
    const float* w      = (const float*)d_in[3];
    float* out = (float*)d_out;

    k_aggregate<<<NBLK, 256>>>(keys, values, w);
    k_mid<<<BH_, 256>>>();
    k_output<<<NBLK, 256>>>(values, out);
}

// round 13
// speedup vs baseline: 1.1453x; 1.1453x over previous
#include <cuda_runtime.h>
#include <math.h>

// Shape fixed by reference: B=2, L=2048, H=16, E=64
#define B_  2
#define L_  2048
#define H_  16
#define E_  64
#define BH_ 32            // B*H chains
#define CH_ 64            // chunk length along s
#define NC_ 32            // chunks per chain
#define HE_ 1024          // H*E row stride in floats
#define NBLK (BH_ * NC_)  // 1024 blocks
#define NSUB 4            // K1 sub-groups (16 rows each)
#define RPS  16           // rows per sub (K1)

// Scratch (__device__ globals; no allocations allowed)
__device__ float  g_E   [BH_ * L_];        // e-scores
__device__ float2 g_agg [NBLK * 32];       // per-chunk sum of e*V (64 ch)
__device__ float  g_aggE[NBLK];            // per-chunk sum of e
__device__ float  g_oct [NBLK * 8 * E_];   // EXCLUSIVE within-chunk EV prefix
                                           // at each 8-row oct start (2 MB)

// ---------------- K1: e-scores + chunk aggregates + oct prefixes -----------
__global__ __launch_bounds__(256, 8) void k_aggregate(
    const float* __restrict__ keys,
    const float* __restrict__ values,
    const float* __restrict__ w_score)
{
    __shared__ float sV[CH_ * E_];     // 16 KB V tile
    __shared__ float se[CH_];
    __shared__ float spEV[NSUB * E_];
    __shared__ float spE[NSUB];

    const int tid = threadIdx.x;
    const int blk = blockIdx.x;
    const int bh  = blk >> 5;          // / NC_
    const int c   = blk & 31;          // % NC_
    const int b   = bh >> 4;
    const int h   = bh & 15;
    const int base = ((b * L_ + c * CH_) * H_ + h) * E_;

    const int d   = tid & 63;
    const int sub = tid >> 6;
    const int r0  = sub * RPS;

    // e[row] = exp(0.125 * dot(K[row], w_k)); 4 threads per row
    {
        const int row = tid >> 2, q = tid & 3;
        const float4* kq = reinterpret_cast<const float4*>(
            keys + base + row * HE_ + q * 16);
        const float4* wq = reinterpret_cast<const float4*>(
            w_score + E_ + q * 16);
        float dot = 0.f;
        #pragma unroll
        for (int j = 0; j < 4; j++) {
            const float4 k4 = kq[j];
            const float4 w4 = wq[j];
            dot += k4.x * w4.x + k4.y * w4.y + k4.z * w4.z + k4.w * w4.w;
        }
        dot += __shfl_xor_sync(0xffffffffu, dot, 1);
        dot += __shfl_xor_sync(0xffffffffu, dot, 2);
        if (q == 0) {
            const float e = __expf(dot * 0.125f);
            se[row] = e;
            g_E[bh * L_ + c * CH_ + row] = e;
        }
    }

    // stage V tile (float4, coalesced)
    {
        const float4* vg = reinterpret_cast<const float4*>(values + base);
        float4* sv4 = reinterpret_cast<float4*>(sV);
        #pragma unroll
        for (int i = 0; i < 4; i++) {
            const int idx = tid + i * 256;
            sv4[idx] = vg[(idx >> 4) * (HE_ / 4) + (idx & 15)];
        }
    }
    __syncthreads();

    // per-sub partial aggregates over 16 rows; capture 8-row midpoint
    float s8;
    {
        float sumE = 0.f, sumEV = 0.f;
        #pragma unroll
        for (int r = 0; r < RPS; r++) {
            const float e = se[r0 + r];
            sumE += e;
            sumEV = fmaf(e, sV[(r0 + r) * E_ + d], sumEV);
            if (r == 7) s8 = sumEV;
        }
        spEV[sub * E_ + d] = sumEV;
        if (d == 0) spE[sub] = sumE;
    }
    __syncthreads();

    // exclusive within-chunk prefixes at oct (8-row) granularity
    {
        float exc = 0.f;
        #pragma unroll
        for (int s = 0; s < NSUB - 1; s++)
            if (s < sub) exc += spEV[s * E_ + d];
        g_oct[(blk * 8 + 2 * sub)     * E_ + d] = exc;
        g_oct[(blk * 8 + 2 * sub + 1) * E_ + d] = exc + s8;
    }

    // block aggregate
    if (tid < E_) {
        reinterpret_cast<float*>(g_agg)[blk * E_ + tid] =
            spEV[tid] + spEV[E_ + tid] + spEV[2 * E_ + tid] + spEV[3 * E_ + tid];
        if (tid == 0)
            g_aggE[blk] = spE[0] + spE[1] + spE[2] + spE[3];
    }
}

// ---------------- K2: float2 output scan, 8 rows/thread, oct layout --------
__global__ __launch_bounds__(256) void k_output(
    const float* __restrict__ values,
    float* __restrict__ out)
{
    __shared__ float  se[CH_];          // e-scores for this chunk
    __shared__ float  srcp[CH_];        // 1 / cumulative-E per row
    __shared__ float2 sq[8 * 32];       // chunk-prefix partials [oct][d2]

    const int tid = threadIdx.x;
    const int blk = blockIdx.x;
    const int bh  = blk >> 5;
    const int c   = blk & 31;
    const int b   = bh >> 4;
    const int h   = bh & 15;
    const int base = ((b * L_ + c * CH_) * H_ + h) * E_;

    const int d2 = tid & 31;            // channel pair (2*d2, 2*d2+1)
    const int o  = tid >> 5;            // oct 0..7 (8 rows)
    const int r0 = o * 8;

    // ---- warp 7: E-side. preE reduce + pair-scan + 2 reciprocals
    if (tid >= 224) {
        const int lane = tid & 31;
        float pe = (lane < c) ? g_aggE[bh * NC_ + lane] : 0.f;
        #pragma unroll
        for (int off = 16; off; off >>= 1)
            pe += __shfl_xor_sync(0xffffffffu, pe, off);
        const float2 e2 = reinterpret_cast<const float2*>(
            g_E + bh * L_ + c * CH_)[lane];
        const float p = e2.x + e2.y;
        float incl = p;
        #pragma unroll
        for (int off = 1; off < 32; off <<= 1) {
            const float t = __shfl_up_sync(0xffffffffu, incl, off);
            if (lane >= off) incl += t;
        }
        const float excl = incl - p;
        se[2 * lane]     = e2.x;
        se[2 * lane + 1] = e2.y;
        srcp[2 * lane]     = __fdividef(1.f, pe + excl + e2.x);
        srcp[2 * lane + 1] = __fdividef(1.f, pe + incl);
    }

    // ---- independent V loads (8 LDG.64, coalesced 256B per row per warp)
    const float2* v2 = reinterpret_cast<const float2*>(values + base);
    float2 vv[8];
    #pragma unroll
    for (int j = 0; j < 8; j++)
        vv[j] = v2[(r0 + j) * (HE_ / 2) + d2];

    // ---- within-chunk exclusive at oct start (one LDG.64)
    float2 acc = reinterpret_cast<const float2*>(g_oct)[(blk * 8 + o) * 32 + d2];

    // ---- chunk-prefix partial: terms t ≡ o (mod 8), t < c  (≤4 LDG.64)
    {
        float2 p = make_float2(0.f, 0.f);
        for (int t = o; t < c; t += 8) {
            const float2 a = g_agg[(bh * NC_ + t) * 32 + d2];
            p.x += a.x; p.y += a.y;
        }
        sq[o * 32 + d2] = p;
    }
    __syncthreads();

    // ---- combine 8 oct partials (8 LDS.64)
    #pragma unroll
    for (int s = 0; s < 8; s++) {
        const float2 t = sq[s * 32 + d2];
        acc.x += t.x; acc.y += t.y;
    }

    // ---- 8-row inclusive scan from regs; float2 stores
    float2* o2 = reinterpret_cast<float2*>(out + base);
    #pragma unroll
    for (int j = 0; j < 8; j++) {
        const float e = se[r0 + j];
        acc.x = fmaf(e, vv[j].x, acc.x);
        acc.y = fmaf(e, vv[j].y, acc.y);
        const float rc = srcp[r0 + j];
        float2 res;
        res.x = acc.x * rc;
        res.y = acc.y * rc;
        o2[(r0 + j) * (HE_ / 2) + d2] = res;
    }
}

extern "C" void kernel_launch(void* const* d_in, const int* in_sizes, int n_in,
                              void* d_out, int out_size) {
    // inputs: 0=queries (unused: a_q cancels in softmax), 1=keys, 2=values,
    //         3=w_score, 4=b_score (unused: cancels)
    const float* keys   = (const float*)d_in[1];
    const float* values = (const float*)d_in[2];
    const float* w      = (const float*)d_in[3];
    float* out = (float*)d_out;

    k_aggregate<<<NBLK, 256>>>(keys, values, w);
    k_output<<<NBLK, 256>>>(values, out);
}